// round 2
// baseline (speedup 1.0000x reference)
#include <cuda_runtime.h>
#include <math.h>
#include <stdint.h>

// Problem dims
#define NB 8
#define NS 1024
#define ND 512
#define NH 8
#define NL 6
#define NF 2048
#define NV 512
#define NM (NB*NS)   // 8192 rows

// Scratch: h, q, k, v, o, tmp (each NM*ND) + ff (NM*NF)  -> ~168 MB static
__device__ float g_scratch[(size_t)6*NM*ND + (size_t)NM*NF];

// ---------------------------------------------------------------------------
// Embedding: h = emb[ids]*sqrt(D) + pe[s]
// ---------------------------------------------------------------------------
__global__ void embed_kernel(const int* __restrict__ ids,
                             const float* __restrict__ emb,
                             const float* __restrict__ pe,
                             float* __restrict__ h)
{
    int i = blockIdx.x * blockDim.x + threadIdx.x;   // over NM*ND/4
    int row = i >> 7;            // ND/4 = 128 float4 per row
    int d4  = (i & 127) << 2;
    int s   = row & (NS - 1);
    int tok = ids[row];
    const float SC = 22.62741699796952f;             // sqrt(512)
    float4 e = *(const float4*)(emb + (size_t)tok * ND + d4);
    float4 p = *(const float4*)(pe  + (size_t)s   * ND + d4);
    float4 r;
    r.x = e.x * SC + p.x; r.y = e.y * SC + p.y;
    r.z = e.z * SC + p.z; r.w = e.w * SC + p.w;
    *(float4*)(h + (size_t)row * ND + d4) = r;
}

// ---------------------------------------------------------------------------
// SGEMM: C[M,N] = A[M,K] @ W[K,N] + bias (+ residual R) (+ ReLU)
// 128x128 tile, BK=8, 256 threads, 8x8 per thread (2x2 quadrants of 4x4)
// ---------------------------------------------------------------------------
template<bool RELU, bool RES>
__global__ void __launch_bounds__(256, 2) sgemm_kernel(
    const float* __restrict__ A, const float* __restrict__ W,
    const float* __restrict__ bias, const float* __restrict__ R,
    float* __restrict__ C, int M, int N, int K)
{
    __shared__ float As[8][128];
    __shared__ float Bs[8][128];
    const int tid = threadIdx.x;
    const int tx = tid & 15;          // 16 col groups
    const int ty = tid >> 4;          // 16 row groups
    const int bn = blockIdx.x * 128;
    const int bm = blockIdx.y * 128;

    const int arow = tid >> 1;
    const int acol = (tid & 1) << 2;
    const int brow = tid >> 5;
    const int bcol = (tid & 31) << 2;

    const float* Ap = A + (size_t)(bm + arow) * K + acol;
    const float* Wp = W + (size_t)brow * N + bn + bcol;

    float acc[8][8];
    #pragma unroll
    for (int i = 0; i < 8; i++)
        #pragma unroll
        for (int j = 0; j < 8; j++) acc[i][j] = 0.f;

    for (int kt = 0; kt < K; kt += 8) {
        float4 a = *(const float4*)(Ap + kt);
        As[acol + 0][arow] = a.x; As[acol + 1][arow] = a.y;
        As[acol + 2][arow] = a.z; As[acol + 3][arow] = a.w;
        *(float4*)&Bs[brow][bcol] = *(const float4*)(Wp + (size_t)kt * N);
        __syncthreads();
        #pragma unroll
        for (int k = 0; k < 8; k++) {
            float ra[8], rb[8];
            *(float4*)(ra)     = *(const float4*)&As[k][ty * 4];
            *(float4*)(ra + 4) = *(const float4*)&As[k][64 + ty * 4];
            *(float4*)(rb)     = *(const float4*)&Bs[k][tx * 4];
            *(float4*)(rb + 4) = *(const float4*)&Bs[k][64 + tx * 4];
            #pragma unroll
            for (int i = 0; i < 8; i++)
                #pragma unroll
                for (int j = 0; j < 8; j++)
                    acc[i][j] = fmaf(ra[i], rb[j], acc[i][j]);
        }
        __syncthreads();
    }

    #pragma unroll
    for (int ih = 0; ih < 2; ih++) {
        #pragma unroll
        for (int i = 0; i < 4; i++) {
            int row = bm + ih * 64 + ty * 4 + i;
            #pragma unroll
            for (int jh = 0; jh < 2; jh++) {
                int col = bn + jh * 64 + tx * 4;
                float4 c;
                c.x = acc[ih * 4 + i][jh * 4 + 0];
                c.y = acc[ih * 4 + i][jh * 4 + 1];
                c.z = acc[ih * 4 + i][jh * 4 + 2];
                c.w = acc[ih * 4 + i][jh * 4 + 3];
                float4 bb = *(const float4*)(bias + col);
                c.x += bb.x; c.y += bb.y; c.z += bb.z; c.w += bb.w;
                if (RES) {
                    float4 r = *(const float4*)(R + (size_t)row * N + col);
                    c.x += r.x; c.y += r.y; c.z += r.z; c.w += r.w;
                }
                if (RELU) {
                    c.x = fmaxf(c.x, 0.f); c.y = fmaxf(c.y, 0.f);
                    c.z = fmaxf(c.z, 0.f); c.w = fmaxf(c.w, 0.f);
                }
                *(float4*)(C + (size_t)row * N + col) = c;
            }
        }
    }
}

// ---------------------------------------------------------------------------
// Flash attention, fp32, with the reference's inverted mask (keep j > i,
// masked value exactly -1e9). Per block: 64 Q rows, one (b,h).
// 128 threads: ty=tid/16 -> 8 rows, tx=tid%16 -> 4 cols.
// smem: Qt[64][64] (d-major), sKP[64][65] (K rows then reused for P), sV[64][68]
// ---------------------------------------------------------------------------
#define ATTN_SMEM_FLOATS (64*64 + 64*65 + 64*68)
#define ATTN_SMEM_BYTES  (ATTN_SMEM_FLOATS * 4)

__global__ void __launch_bounds__(128) attn_kernel(
    const float* __restrict__ Q, const float* __restrict__ K,
    const float* __restrict__ V, float* __restrict__ O)
{
    extern __shared__ float sm[];
    float* Qt  = sm;                      // Qt[d*64 + i]
    float* sKP = sm + 64 * 64;            // sK[j*65 + d]  /  sP[i*65 + j]
    float* sV  = sm + 64 * 64 + 64 * 65;  // sV[j*68 + d]

    const int tid = threadIdx.x;
    const int tx = tid & 15;
    const int ty = tid >> 4;
    const int qb = blockIdx.x, h = blockIdx.y, b = blockIdx.z;

    const size_t base = ((size_t)b * NS) * ND + h * 64;
    const float* Qg = Q + base + (size_t)(qb * 64) * ND;
    const float* Kg = K + base;
    const float* Vg = V + base;

    // Load Q tile transposed: Qt[d][i] = Q[i][d]
    {
        int r = tid >> 4;               // 0..7
        int d = (tid & 15) * 4;
        #pragma unroll
        for (int p = 0; p < 8; p++) {
            int rr = r + p * 8;
            float4 qv = *(const float4*)(Qg + (size_t)rr * ND + d);
            Qt[(d + 0) * 64 + rr] = qv.x;
            Qt[(d + 1) * 64 + rr] = qv.y;
            Qt[(d + 2) * 64 + rr] = qv.z;
            Qt[(d + 3) * 64 + rr] = qv.w;
        }
    }

    float m[8], l[8], o[8][4];
    #pragma unroll
    for (int i = 0; i < 8; i++) {
        m[i] = -1e30f; l[i] = 0.f;
        o[i][0] = o[i][1] = o[i][2] = o[i][3] = 0.f;
    }

    const int igb = qb * 64 + ty * 8;

    for (int t = 0; t < NS / 64; t++) {
        // Load K (row-major into sKP) and V tiles
        {
            int r = tid >> 4;
            int d = (tid & 15) * 4;
            #pragma unroll
            for (int p = 0; p < 8; p++) {
                int rr = r + p * 8;
                float4 kv = *(const float4*)(Kg + (size_t)(t * 64 + rr) * ND + d);
                sKP[rr * 65 + d + 0] = kv.x;
                sKP[rr * 65 + d + 1] = kv.y;
                sKP[rr * 65 + d + 2] = kv.z;
                sKP[rr * 65 + d + 3] = kv.w;
                float4 vv = *(const float4*)(Vg + (size_t)(t * 64 + rr) * ND + d);
                *(float4*)&sV[rr * 68 + d] = vv;
            }
        }
        __syncthreads();

        // Scores: s[i][j] = sum_d Q[row][d] * K[col][d]
        float s[8][4];
        #pragma unroll
        for (int i = 0; i < 8; i++)
            s[i][0] = s[i][1] = s[i][2] = s[i][3] = 0.f;
        #pragma unroll 8
        for (int d = 0; d < 64; d++) {
            float ra[8];
            *(float4*)(ra)     = *(const float4*)&Qt[d * 64 + ty * 8];
            *(float4*)(ra + 4) = *(const float4*)&Qt[d * 64 + ty * 8 + 4];
            float rb[4];
            rb[0] = sKP[(tx * 4 + 0) * 65 + d];
            rb[1] = sKP[(tx * 4 + 1) * 65 + d];
            rb[2] = sKP[(tx * 4 + 2) * 65 + d];
            rb[3] = sKP[(tx * 4 + 3) * 65 + d];
            #pragma unroll
            for (int i = 0; i < 8; i++)
                #pragma unroll
                for (int j = 0; j < 4; j++)
                    s[i][j] = fmaf(ra[i], rb[j], s[i][j]);
        }

        // Mask (keep strictly j > i) + online softmax (16-lane row groups)
        const int jgb = t * 64 + tx * 4;
        #pragma unroll
        for (int i = 0; i < 8; i++) {
            int igr = igb + i;
            #pragma unroll
            for (int j = 0; j < 4; j++)
                s[i][j] = (jgb + j > igr) ? s[i][j] * 0.125f : -1e9f;
            float mx = fmaxf(fmaxf(s[i][0], s[i][1]), fmaxf(s[i][2], s[i][3]));
            mx = fmaxf(mx, __shfl_xor_sync(0xffffffffu, mx, 1));
            mx = fmaxf(mx, __shfl_xor_sync(0xffffffffu, mx, 2));
            mx = fmaxf(mx, __shfl_xor_sync(0xffffffffu, mx, 4));
            mx = fmaxf(mx, __shfl_xor_sync(0xffffffffu, mx, 8));
            float mn = fmaxf(m[i], mx);
            float corr = __expf(m[i] - mn);
            float ls = 0.f;
            #pragma unroll
            for (int j = 0; j < 4; j++) {
                float p = __expf(s[i][j] - mn);
                s[i][j] = p; ls += p;
            }
            ls += __shfl_xor_sync(0xffffffffu, ls, 1);
            ls += __shfl_xor_sync(0xffffffffu, ls, 2);
            ls += __shfl_xor_sync(0xffffffffu, ls, 4);
            ls += __shfl_xor_sync(0xffffffffu, ls, 8);
            l[i] = l[i] * corr + ls;
            m[i] = mn;
            o[i][0] *= corr; o[i][1] *= corr; o[i][2] *= corr; o[i][3] *= corr;
        }
        __syncthreads();   // everyone done reading sKP as K

        // Write P transposed into sKP as sP[i][j]
        #pragma unroll
        for (int i = 0; i < 8; i++) {
            int row = ty * 8 + i;
            sKP[row * 65 + tx * 4 + 0] = s[i][0];
            sKP[row * 65 + tx * 4 + 1] = s[i][1];
            sKP[row * 65 + tx * 4 + 2] = s[i][2];
            sKP[row * 65 + tx * 4 + 3] = s[i][3];
        }
        __syncthreads();

        // O += P @ V
        #pragma unroll 8
        for (int j = 0; j < 64; j++) {
            float vb[4];
            *(float4*)vb = *(const float4*)&sV[j * 68 + tx * 4];
            #pragma unroll
            for (int i = 0; i < 8; i++) {
                float p = sKP[(ty * 8 + i) * 65 + j];
                o[i][0] = fmaf(p, vb[0], o[i][0]);
                o[i][1] = fmaf(p, vb[1], o[i][1]);
                o[i][2] = fmaf(p, vb[2], o[i][2]);
                o[i][3] = fmaf(p, vb[3], o[i][3]);
            }
        }
        __syncthreads();   // done with sKP/sV before next tile load
    }

    // Normalize and write
    float* Og = O + base + (size_t)(qb * 64) * ND;
    #pragma unroll
    for (int i = 0; i < 8; i++) {
        float inv = 1.0f / l[i];
        float4 r;
        r.x = o[i][0] * inv; r.y = o[i][1] * inv;
        r.z = o[i][2] * inv; r.w = o[i][3] * inv;
        *(float4*)(Og + (size_t)(ty * 8 + i) * ND + tx * 4) = r;
    }
}

// ---------------------------------------------------------------------------
// LayerNorm: warp per row (D=512, 16 elems/lane)
// ---------------------------------------------------------------------------
__global__ void ln_kernel(const float* __restrict__ X, const float* __restrict__ gam,
                          const float* __restrict__ bet, float* __restrict__ Y)
{
    int row  = blockIdx.x * 4 + (threadIdx.x >> 5);
    int lane = threadIdx.x & 31;
    const float* x = X + (size_t)row * ND;
    float4 v[4];
    float sum = 0.f;
    #pragma unroll
    for (int i = 0; i < 4; i++) {
        v[i] = *(const float4*)(x + lane * 4 + i * 128);
        sum += v[i].x + v[i].y + v[i].z + v[i].w;
    }
    #pragma unroll
    for (int off = 16; off; off >>= 1) sum += __shfl_xor_sync(0xffffffffu, sum, off);
    float mu = sum * (1.0f / 512.0f);
    float vs = 0.f;
    #pragma unroll
    for (int i = 0; i < 4; i++) {
        float dx;
        dx = v[i].x - mu; vs += dx * dx;
        dx = v[i].y - mu; vs += dx * dx;
        dx = v[i].z - mu; vs += dx * dx;
        dx = v[i].w - mu; vs += dx * dx;
    }
    #pragma unroll
    for (int off = 16; off; off >>= 1) vs += __shfl_xor_sync(0xffffffffu, vs, off);
    float rstd = rsqrtf(vs * (1.0f / 512.0f) + 1e-5f);
    float* y = Y + (size_t)row * ND;
    #pragma unroll
    for (int i = 0; i < 4; i++) {
        float4 g4 = *(const float4*)(gam + lane * 4 + i * 128);
        float4 b4 = *(const float4*)(bet + lane * 4 + i * 128);
        float4 r;
        r.x = (v[i].x - mu) * rstd * g4.x + b4.x;
        r.y = (v[i].y - mu) * rstd * g4.y + b4.y;
        r.z = (v[i].z - mu) * rstd * g4.z + b4.z;
        r.w = (v[i].w - mu) * rstd * g4.w + b4.w;
        *(float4*)(y + lane * 4 + i * 128) = r;
    }
}

// ---------------------------------------------------------------------------
// Host orchestration
// ---------------------------------------------------------------------------
extern "C" void kernel_launch(void* const* d_in, const int* in_sizes, int n_in,
                              void* d_out, int out_size)
{
    const int*   ids  = (const int*)  d_in[0];
    const float* emb  = (const float*)d_in[1];
    const float* pe   = (const float*)d_in[2];
    const float* Wq   = (const float*)d_in[3];
    const float* bq   = (const float*)d_in[4];
    const float* Wk   = (const float*)d_in[5];
    const float* bk   = (const float*)d_in[6];
    const float* Wv   = (const float*)d_in[7];
    const float* bv   = (const float*)d_in[8];
    const float* Wo   = (const float*)d_in[9];
    const float* bo   = (const float*)d_in[10];
    const float* g1   = (const float*)d_in[11];
    const float* be1  = (const float*)d_in[12];
    const float* W1   = (const float*)d_in[13];
    const float* b1   = (const float*)d_in[14];
    const float* W2   = (const float*)d_in[15];
    const float* b2   = (const float*)d_in[16];
    const float* g2   = (const float*)d_in[17];
    const float* be2  = (const float*)d_in[18];
    const float* Wout = (const float*)d_in[19];
    const float* bout = (const float*)d_in[20];
    float* out = (float*)d_out;

    float* scratch = nullptr;
    cudaGetSymbolAddress((void**)&scratch, g_scratch);
    float* h  = scratch;
    float* q  = h  + (size_t)NM * ND;
    float* k  = q  + (size_t)NM * ND;
    float* v  = k  + (size_t)NM * ND;
    float* o  = v  + (size_t)NM * ND;
    float* tp = o  + (size_t)NM * ND;
    float* ff = tp + (size_t)NM * ND;

    cudaFuncSetAttribute(attn_kernel, cudaFuncAttributeMaxDynamicSharedMemorySize,
                         ATTN_SMEM_BYTES);

    embed_kernel<<<(NM * ND / 4) / 256, 256>>>(ids, emb, pe, h);

    dim3 gP (ND / 128, NM / 128);   // projections: N=512
    dim3 gF1(NF / 128, NM / 128);   // FFN1: N=2048
    dim3 attG(NS / 64, NH, NB);

    for (int L = 0; L < NL; L++) {
        size_t wo  = (size_t)L * ND * ND;
        size_t bo_ = (size_t)L * ND;
        sgemm_kernel<false, false><<<gP, 256>>>(h, Wq + wo, bq + bo_, nullptr, q, NM, ND, ND);
        sgemm_kernel<false, false><<<gP, 256>>>(h, Wk + wo, bk + bo_, nullptr, k, NM, ND, ND);
        sgemm_kernel<false, false><<<gP, 256>>>(h, Wv + wo, bv + bo_, nullptr, v, NM, ND, ND);
        attn_kernel<<<attG, 128, ATTN_SMEM_BYTES>>>(q, k, v, o);
        sgemm_kernel<false, true ><<<gP, 256>>>(o, Wo + wo, bo + bo_, h, tp, NM, ND, ND);
        ln_kernel<<<NM / 4, 128>>>(tp, g1 + bo_, be1 + bo_, h);
        sgemm_kernel<true,  false><<<gF1, 256>>>(h, W1 + (size_t)L * ND * NF,
                                                 b1 + (size_t)L * NF, nullptr, ff, NM, NF, ND);
        sgemm_kernel<false, true ><<<gP, 256>>>(ff, W2 + (size_t)L * NF * ND,
                                                b2 + bo_, h, tp, NM, ND, NF);
        ln_kernel<<<NM / 4, 128>>>(tp, g2 + bo_, be2 + bo_, h);
    }
    sgemm_kernel<false, false><<<dim3(NV / 128, NM / 128), 256>>>(
        h, Wout, bout, nullptr, out, NM, NV, ND);
}

// round 4
// speedup vs baseline: 1.5127x; 1.5127x over previous
#include <cuda_runtime.h>
#include <math.h>
#include <stdint.h>

// Problem dims
#define NB 8
#define NS 1024
#define ND 512
#define NH 8
#define NL 6
#define NF 2048
#define NV 512
#define NM (NB*NS)   // 8192 rows

// Scratch: h, q, k, v, o, tmp (each NM*ND) + ff (NM*NF)
__device__ float g_scratch[(size_t)6*NM*ND + (size_t)NM*NF];

// ---------------------------------------------------------------------------
// Embedding: h = emb[ids]*sqrt(D) + pe[s]
// ---------------------------------------------------------------------------
__global__ void embed_kernel(const int* __restrict__ ids,
                             const float* __restrict__ emb,
                             const float* __restrict__ pe,
                             float* __restrict__ h)
{
    int i = blockIdx.x * blockDim.x + threadIdx.x;
    int row = i >> 7;
    int d4  = (i & 127) << 2;
    int s   = row & (NS - 1);
    int tok = ids[row];
    const float SC = 22.62741699796952f;
    float4 e = *(const float4*)(emb + (size_t)tok * ND + d4);
    float4 p = *(const float4*)(pe  + (size_t)s   * ND + d4);
    float4 r;
    r.x = e.x * SC + p.x; r.y = e.y * SC + p.y;
    r.z = e.z * SC + p.z; r.w = e.w * SC + p.w;
    *(float4*)(h + (size_t)row * ND + d4) = r;
}

// ---------------------------------------------------------------------------
// TF32 helpers
// ---------------------------------------------------------------------------
__device__ __forceinline__ float tf32r(float x) {
    uint32_t y;
    asm("cvt.rna.tf32.f32 %0, %1;" : "=r"(y) : "f"(x));
    return __uint_as_float(y);
}

__device__ __forceinline__ void mma_tf32(float c[4], const uint32_t a[4],
                                         const uint32_t b[2]) {
    asm volatile(
        "mma.sync.aligned.m16n8k8.row.col.f32.tf32.tf32.f32 "
        "{%0,%1,%2,%3}, {%4,%5,%6,%7}, {%8,%9}, {%0,%1,%2,%3};\n"
        : "+f"(c[0]), "+f"(c[1]), "+f"(c[2]), "+f"(c[3])
        : "r"(a[0]), "r"(a[1]), "r"(a[2]), "r"(a[3]),
          "r"(b[0]), "r"(b[1]));
}

// ---------------------------------------------------------------------------
// TF32 MMA GEMM: C[M,N] = A[M,K] @ W[K,N] + bias (+R) (+ReLU)
// 128x128 tile, BK=32, 256 threads = 8 warps (4m x 2n), warp tile 32x64.
// As[m][36] pad -> conflict-free frag reads; Bs[k][132] likewise.
// ---------------------------------------------------------------------------
#define BKK 32
#define APAD 36
#define BPAD 132

template<bool RELU, bool RES>
__global__ void __launch_bounds__(256, 2) mma_gemm(
    const float* __restrict__ A, const float* __restrict__ W,
    const float* __restrict__ bias, const float* __restrict__ R,
    float* __restrict__ C, int M, int N, int K)
{
    __shared__ float As[128][APAD];   // [m][k]
    __shared__ float Bs[BKK][BPAD];   // [k][n]

    const int tid  = threadIdx.x;
    const int lane = tid & 31;
    const int warp = tid >> 5;
    const int wm = (warp >> 1) * 32;
    const int wn = (warp & 1) * 64;
    const int bm = blockIdx.y * 128;
    const int bn = blockIdx.x * 128;

    const int arow = tid >> 1;
    const int acol = (tid & 1) * 16;
    const int brow = tid >> 3;
    const int bcol = (tid & 7) * 16;

    const float* Ap = A + (size_t)(bm + arow) * K + acol;
    const float* Wp = W + (size_t)brow * N + bn + bcol;

    float acc[2][8][4];
    #pragma unroll
    for (int mf = 0; mf < 2; mf++)
        #pragma unroll
        for (int nf = 0; nf < 8; nf++)
            #pragma unroll
            for (int i = 0; i < 4; i++) acc[mf][nf][i] = 0.f;

    float4 pa[4], pb[4];
    #pragma unroll
    for (int i = 0; i < 4; i++) {
        pa[i] = *(const float4*)(Ap + i * 4);
        pb[i] = *(const float4*)(Wp + i * 4);
    }
    #pragma unroll
    for (int i = 0; i < 4; i++) {
        float4 t = pa[i];
        float4 v = make_float4(tf32r(t.x), tf32r(t.y), tf32r(t.z), tf32r(t.w));
        *(float4*)&As[arow][acol + i * 4] = v;
        t = pb[i];
        v = make_float4(tf32r(t.x), tf32r(t.y), tf32r(t.z), tf32r(t.w));
        *(float4*)&Bs[brow][bcol + i * 4] = v;
    }
    __syncthreads();

    const int lg = lane >> 2;      // groupID
    const int lt = lane & 3;       // thread-in-group

    for (int kt = 0; kt < K; kt += BKK) {
        const bool more = (kt + BKK) < K;
        if (more) {
            #pragma unroll
            for (int i = 0; i < 4; i++) {
                pa[i] = *(const float4*)(Ap + kt + BKK + i * 4);
                pb[i] = *(const float4*)(Wp + (size_t)(kt + BKK) * N + i * 4);
            }
        }

        #pragma unroll
        for (int kk = 0; kk < BKK; kk += 8) {
            const int kb = kk + lt;
            uint32_t af[2][4];
            #pragma unroll
            for (int mf = 0; mf < 2; mf++) {
                int r0 = wm + mf * 16 + lg;
                af[mf][0] = __float_as_uint(As[r0][kb]);
                af[mf][1] = __float_as_uint(As[r0 + 8][kb]);
                af[mf][2] = __float_as_uint(As[r0][kb + 4]);
                af[mf][3] = __float_as_uint(As[r0 + 8][kb + 4]);
            }
            #pragma unroll
            for (int nf = 0; nf < 8; nf++) {
                uint32_t bf[2];
                int nc = wn + nf * 8 + lg;
                bf[0] = __float_as_uint(Bs[kb][nc]);
                bf[1] = __float_as_uint(Bs[kb + 4][nc]);
                mma_tf32(acc[0][nf], af[0], bf);
                mma_tf32(acc[1][nf], af[1], bf);
            }
        }
        __syncthreads();
        if (more) {
            #pragma unroll
            for (int i = 0; i < 4; i++) {
                float4 t = pa[i];
                float4 v = make_float4(tf32r(t.x), tf32r(t.y), tf32r(t.z), tf32r(t.w));
                *(float4*)&As[arow][acol + i * 4] = v;
                t = pb[i];
                v = make_float4(tf32r(t.x), tf32r(t.y), tf32r(t.z), tf32r(t.w));
                *(float4*)&Bs[brow][bcol + i * 4] = v;
            }
            __syncthreads();
        }
    }

    // Epilogue
    #pragma unroll
    for (int mf = 0; mf < 2; mf++) {
        int r0 = bm + wm + mf * 16 + lg;
        int r1 = r0 + 8;
        #pragma unroll
        for (int nf = 0; nf < 8; nf++) {
            int col = bn + wn + nf * 8 + lt * 2;
            float2 bb = *(const float2*)(bias + col);
            float c0 = acc[mf][nf][0] + bb.x;
            float c1 = acc[mf][nf][1] + bb.y;
            float c2 = acc[mf][nf][2] + bb.x;
            float c3 = acc[mf][nf][3] + bb.y;
            if (RES) {
                float2 ra = *(const float2*)(R + (size_t)r0 * N + col);
                float2 rb = *(const float2*)(R + (size_t)r1 * N + col);
                c0 += ra.x; c1 += ra.y; c2 += rb.x; c3 += rb.y;
            }
            if (RELU) {
                c0 = fmaxf(c0, 0.f); c1 = fmaxf(c1, 0.f);
                c2 = fmaxf(c2, 0.f); c3 = fmaxf(c3, 0.f);
            }
            *(float2*)(C + (size_t)r0 * N + col) = make_float2(c0, c1);
            *(float2*)(C + (size_t)r1 * N + col) = make_float2(c2, c3);
        }
    }
}

// ---------------------------------------------------------------------------
// Flash attention (fp32), reference's inverted mask (keep j > i, fill -1e9)
// ---------------------------------------------------------------------------
#define ATTN_SMEM_FLOATS (64*64 + 64*65 + 64*68)
#define ATTN_SMEM_BYTES  (ATTN_SMEM_FLOATS * 4)

__global__ void __launch_bounds__(128) attn_kernel(
    const float* __restrict__ Q, const float* __restrict__ K,
    const float* __restrict__ V, float* __restrict__ O)
{
    extern __shared__ float sm[];
    float* Qt  = sm;
    float* sKP = sm + 64 * 64;
    float* sV  = sm + 64 * 64 + 64 * 65;

    const int tid = threadIdx.x;
    const int tx = tid & 15;
    const int ty = tid >> 4;
    const int qb = blockIdx.x, h = blockIdx.y, b = blockIdx.z;

    const size_t base = ((size_t)b * NS) * ND + h * 64;
    const float* Qg = Q + base + (size_t)(qb * 64) * ND;
    const float* Kg = K + base;
    const float* Vg = V + base;

    {
        int r = tid >> 4;
        int d = (tid & 15) * 4;
        #pragma unroll
        for (int p = 0; p < 8; p++) {
            int rr = r + p * 8;
            float4 qv = *(const float4*)(Qg + (size_t)rr * ND + d);
            Qt[(d + 0) * 64 + rr] = qv.x;
            Qt[(d + 1) * 64 + rr] = qv.y;
            Qt[(d + 2) * 64 + rr] = qv.z;
            Qt[(d + 3) * 64 + rr] = qv.w;
        }
    }

    float m[8], l[8], o[8][4];
    #pragma unroll
    for (int i = 0; i < 8; i++) {
        m[i] = -1e30f; l[i] = 0.f;
        o[i][0] = o[i][1] = o[i][2] = o[i][3] = 0.f;
    }

    const int igb = qb * 64 + ty * 8;

    for (int t = 0; t < NS / 64; t++) {
        {
            int r = tid >> 4;
            int d = (tid & 15) * 4;
            #pragma unroll
            for (int p = 0; p < 8; p++) {
                int rr = r + p * 8;
                float4 kv = *(const float4*)(Kg + (size_t)(t * 64 + rr) * ND + d);
                sKP[rr * 65 + d + 0] = kv.x;
                sKP[rr * 65 + d + 1] = kv.y;
                sKP[rr * 65 + d + 2] = kv.z;
                sKP[rr * 65 + d + 3] = kv.w;
                float4 vv = *(const float4*)(Vg + (size_t)(t * 64 + rr) * ND + d);
                *(float4*)&sV[rr * 68 + d] = vv;
            }
        }
        __syncthreads();

        float s[8][4];
        #pragma unroll
        for (int i = 0; i < 8; i++)
            s[i][0] = s[i][1] = s[i][2] = s[i][3] = 0.f;
        #pragma unroll 8
        for (int d = 0; d < 64; d++) {
            float ra[8];
            *(float4*)(ra)     = *(const float4*)&Qt[d * 64 + ty * 8];
            *(float4*)(ra + 4) = *(const float4*)&Qt[d * 64 + ty * 8 + 4];
            float rb[4];
            rb[0] = sKP[(tx * 4 + 0) * 65 + d];
            rb[1] = sKP[(tx * 4 + 1) * 65 + d];
            rb[2] = sKP[(tx * 4 + 2) * 65 + d];
            rb[3] = sKP[(tx * 4 + 3) * 65 + d];
            #pragma unroll
            for (int i = 0; i < 8; i++)
                #pragma unroll
                for (int j = 0; j < 4; j++)
                    s[i][j] = fmaf(ra[i], rb[j], s[i][j]);
        }

        const int jgb = t * 64 + tx * 4;
        #pragma unroll
        for (int i = 0; i < 8; i++) {
            int igr = igb + i;
            #pragma unroll
            for (int j = 0; j < 4; j++)
                s[i][j] = (jgb + j > igr) ? s[i][j] * 0.125f : -1e9f;
            float mx = fmaxf(fmaxf(s[i][0], s[i][1]), fmaxf(s[i][2], s[i][3]));
            mx = fmaxf(mx, __shfl_xor_sync(0xffffffffu, mx, 1));
            mx = fmaxf(mx, __shfl_xor_sync(0xffffffffu, mx, 2));
            mx = fmaxf(mx, __shfl_xor_sync(0xffffffffu, mx, 4));
            mx = fmaxf(mx, __shfl_xor_sync(0xffffffffu, mx, 8));
            float mn = fmaxf(m[i], mx);
            float corr = __expf(m[i] - mn);
            float ls = 0.f;
            #pragma unroll
            for (int j = 0; j < 4; j++) {
                float p = __expf(s[i][j] - mn);
                s[i][j] = p; ls += p;
            }
            ls += __shfl_xor_sync(0xffffffffu, ls, 1);
            ls += __shfl_xor_sync(0xffffffffu, ls, 2);
            ls += __shfl_xor_sync(0xffffffffu, ls, 4);
            ls += __shfl_xor_sync(0xffffffffu, ls, 8);
            l[i] = l[i] * corr + ls;
            m[i] = mn;
            o[i][0] *= corr; o[i][1] *= corr; o[i][2] *= corr; o[i][3] *= corr;
        }
        __syncthreads();

        #pragma unroll
        for (int i = 0; i < 8; i++) {
            int row = ty * 8 + i;
            sKP[row * 65 + tx * 4 + 0] = s[i][0];
            sKP[row * 65 + tx * 4 + 1] = s[i][1];
            sKP[row * 65 + tx * 4 + 2] = s[i][2];
            sKP[row * 65 + tx * 4 + 3] = s[i][3];
        }
        __syncthreads();

        #pragma unroll 8
        for (int j = 0; j < 64; j++) {
            float vb[4];
            *(float4*)vb = *(const float4*)&sV[j * 68 + tx * 4];
            #pragma unroll
            for (int i = 0; i < 8; i++) {
                float p = sKP[(ty * 8 + i) * 65 + j];
                o[i][0] = fmaf(p, vb[0], o[i][0]);
                o[i][1] = fmaf(p, vb[1], o[i][1]);
                o[i][2] = fmaf(p, vb[2], o[i][2]);
                o[i][3] = fmaf(p, vb[3], o[i][3]);
            }
        }
        __syncthreads();
    }

    float* Og = O + base + (size_t)(qb * 64) * ND;
    #pragma unroll
    for (int i = 0; i < 8; i++) {
        float inv = 1.0f / l[i];
        float4 r;
        r.x = o[i][0] * inv; r.y = o[i][1] * inv;
        r.z = o[i][2] * inv; r.w = o[i][3] * inv;
        *(float4*)(Og + (size_t)(ty * 8 + i) * ND + tx * 4) = r;
    }
}

// ---------------------------------------------------------------------------
// LayerNorm: warp per row
// ---------------------------------------------------------------------------
__global__ void ln_kernel(const float* __restrict__ X, const float* __restrict__ gam,
                          const float* __restrict__ bet, float* __restrict__ Y)
{
    int row  = blockIdx.x * 4 + (threadIdx.x >> 5);
    int lane = threadIdx.x & 31;
    const float* x = X + (size_t)row * ND;
    float4 v[4];
    float sum = 0.f;
    #pragma unroll
    for (int i = 0; i < 4; i++) {
        v[i] = *(const float4*)(x + lane * 4 + i * 128);
        sum += v[i].x + v[i].y + v[i].z + v[i].w;
    }
    #pragma unroll
    for (int off = 16; off; off >>= 1) sum += __shfl_xor_sync(0xffffffffu, sum, off);
    float mu = sum * (1.0f / 512.0f);
    float vs = 0.f;
    #pragma unroll
    for (int i = 0; i < 4; i++) {
        float dx;
        dx = v[i].x - mu; vs += dx * dx;
        dx = v[i].y - mu; vs += dx * dx;
        dx = v[i].z - mu; vs += dx * dx;
        dx = v[i].w - mu; vs += dx * dx;
    }
    #pragma unroll
    for (int off = 16; off; off >>= 1) vs += __shfl_xor_sync(0xffffffffu, vs, off);
    float rstd = rsqrtf(vs * (1.0f / 512.0f) + 1e-5f);
    float* y = Y + (size_t)row * ND;
    #pragma unroll
    for (int i = 0; i < 4; i++) {
        float4 g4 = *(const float4*)(gam + lane * 4 + i * 128);
        float4 b4 = *(const float4*)(bet + lane * 4 + i * 128);
        float4 r;
        r.x = (v[i].x - mu) * rstd * g4.x + b4.x;
        r.y = (v[i].y - mu) * rstd * g4.y + b4.y;
        r.z = (v[i].z - mu) * rstd * g4.z + b4.z;
        r.w = (v[i].w - mu) * rstd * g4.w + b4.w;
        *(float4*)(y + lane * 4 + i * 128) = r;
    }
}

// ---------------------------------------------------------------------------
// Host orchestration
// ---------------------------------------------------------------------------
extern "C" void kernel_launch(void* const* d_in, const int* in_sizes, int n_in,
                              void* d_out, int out_size)
{
    const int*   ids  = (const int*)  d_in[0];
    const float* emb  = (const float*)d_in[1];
    const float* pe   = (const float*)d_in[2];
    const float* Wq   = (const float*)d_in[3];
    const float* bq   = (const float*)d_in[4];
    const float* Wk   = (const float*)d_in[5];
    const float* bk   = (const float*)d_in[6];
    const float* Wv   = (const float*)d_in[7];
    const float* bv   = (const float*)d_in[8];
    const float* Wo   = (const float*)d_in[9];
    const float* bo   = (const float*)d_in[10];
    const float* g1   = (const float*)d_in[11];
    const float* be1  = (const float*)d_in[12];
    const float* W1   = (const float*)d_in[13];
    const float* b1   = (const float*)d_in[14];
    const float* W2   = (const float*)d_in[15];
    const float* b2   = (const float*)d_in[16];
    const float* g2   = (const float*)d_in[17];
    const float* be2  = (const float*)d_in[18];
    const float* Wout = (const float*)d_in[19];
    const float* bout = (const float*)d_in[20];
    float* out = (float*)d_out;

    float* scratch = nullptr;
    cudaGetSymbolAddress((void**)&scratch, g_scratch);
    float* h  = scratch;
    float* q  = h  + (size_t)NM * ND;
    float* k  = q  + (size_t)NM * ND;
    float* v  = k  + (size_t)NM * ND;
    float* o  = v  + (size_t)NM * ND;
    float* tp = o  + (size_t)NM * ND;
    float* ff = tp + (size_t)NM * ND;

    cudaFuncSetAttribute(attn_kernel, cudaFuncAttributeMaxDynamicSharedMemorySize,
                         ATTN_SMEM_BYTES);

    embed_kernel<<<(NM * ND / 4) / 256, 256>>>(ids, emb, pe, h);

    dim3 gP (ND / 128, NM / 128);
    dim3 gF1(NF / 128, NM / 128);
    dim3 attG(NS / 64, NH, NB);

    for (int L = 0; L < NL; L++) {
        size_t wo  = (size_t)L * ND * ND;
        size_t bo_ = (size_t)L * ND;
        mma_gemm<false, false><<<gP, 256>>>(h, Wq + wo, bq + bo_, nullptr, q, NM, ND, ND);
        mma_gemm<false, false><<<gP, 256>>>(h, Wk + wo, bk + bo_, nullptr, k, NM, ND, ND);
        mma_gemm<false, false><<<gP, 256>>>(h, Wv + wo, bv + bo_, nullptr, v, NM, ND, ND);
        attn_kernel<<<attG, 128, ATTN_SMEM_BYTES>>>(q, k, v, o);
        mma_gemm<false, true ><<<gP, 256>>>(o, Wo + wo, bo + bo_, h, tp, NM, ND, ND);
        ln_kernel<<<NM / 4, 128>>>(tp, g1 + bo_, be1 + bo_, h);
        mma_gemm<true,  false><<<gF1, 256>>>(h, W1 + (size_t)L * ND * NF,
                                             b1 + (size_t)L * NF, nullptr, ff, NM, NF, ND);
        mma_gemm<false, true ><<<gP, 256>>>(ff, W2 + (size_t)L * NF * ND,
                                            b2 + bo_, h, tp, NM, ND, NF);
        ln_kernel<<<NM / 4, 128>>>(tp, g2 + bo_, be2 + bo_, h);
    }
    mma_gemm<false, false><<<dim3(NV / 128, NM / 128), 256>>>(
        h, Wout, bout, nullptr, out, NM, NV, ND);
}

// round 5
// speedup vs baseline: 1.7256x; 1.1408x over previous
#include <cuda_runtime.h>
#include <math.h>
#include <stdint.h>

// Problem dims
#define NB 8
#define NS 1024
#define ND 512
#define NH 8
#define NL 6
#define NF 2048
#define NV 512
#define NM (NB*NS)   // 8192 rows

// ---------------------------------------------------------------------------
// Scratch layout (floats):
// h, h_r, o, tp: NM*ND each;  qkv: NM*1536;  ff: NM*NF
// Wqkv_r: L*512*1536; Wo_r: L*512*512; W1_r: L*512*2048; W2_r: L*2048*512;
// Wout_r: 512*512; bqkv: L*1536
// ---------------------------------------------------------------------------
#define SZ_HD   ((size_t)NM*ND)
#define SZ_QKV  ((size_t)NM*1536)
#define SZ_FF   ((size_t)NM*NF)
#define SZ_WQKV ((size_t)NL*512*1536)
#define SZ_WO   ((size_t)NL*512*512)
#define SZ_W1   ((size_t)NL*512*2048)
#define SZ_W2   ((size_t)NL*2048*512)
#define SZ_WOUT ((size_t)512*512)
#define SZ_BQKV ((size_t)NL*1536)

__device__ float g_scratch[4*SZ_HD + SZ_QKV + SZ_FF + SZ_WQKV + SZ_WO +
                           SZ_W1 + SZ_W2 + SZ_WOUT + SZ_BQKV];

// ---------------------------------------------------------------------------
// TF32 helpers
// ---------------------------------------------------------------------------
__device__ __forceinline__ float tf32r(float x) {
    uint32_t y;
    asm("cvt.rna.tf32.f32 %0, %1;" : "=r"(y) : "f"(x));
    return __uint_as_float(y);
}

__device__ __forceinline__ void mma_tf32(float c[4], const float a[4],
                                         const float b[2]) {
    asm volatile(
        "mma.sync.aligned.m16n8k8.row.col.f32.tf32.tf32.f32 "
        "{%0,%1,%2,%3}, {%4,%5,%6,%7}, {%8,%9}, {%0,%1,%2,%3};\n"
        : "+f"(c[0]), "+f"(c[1]), "+f"(c[2]), "+f"(c[3])
        : "r"(__float_as_uint(a[0])), "r"(__float_as_uint(a[1])),
          "r"(__float_as_uint(a[2])), "r"(__float_as_uint(a[3])),
          "r"(__float_as_uint(b[0])), "r"(__float_as_uint(b[1])));
}

__device__ __forceinline__ void cpa16(uint32_t dst, const void* src) {
    asm volatile("cp.async.ca.shared.global [%0], [%1], 16;\n"
                 :: "r"(dst), "l"(src));
}
__device__ __forceinline__ void cpa_commit() {
    asm volatile("cp.async.commit_group;\n" ::);
}
__device__ __forceinline__ void cpa_wait1() {
    asm volatile("cp.async.wait_group 1;\n" ::);
}

// ---------------------------------------------------------------------------
// Weight pre-round / pack kernels (run every launch; deterministic)
// ---------------------------------------------------------------------------
__global__ void round_copy4(const float* __restrict__ src, float* __restrict__ dst) {
    size_t i = ((size_t)blockIdx.x * 256 + threadIdx.x) * 4;
    float4 v = *(const float4*)(src + i);
    v.x = tf32r(v.x); v.y = tf32r(v.y); v.z = tf32r(v.z); v.w = tf32r(v.w);
    *(float4*)(dst + i) = v;
}

__global__ void pack_qkv_w(const float* __restrict__ Wq, const float* __restrict__ Wk,
                           const float* __restrict__ Wv, float* __restrict__ dst) {
    size_t i = ((size_t)blockIdx.x * 256 + threadIdx.x);     // over L*512*384 float4
    size_t e = i * 4;
    size_t l  = e / (512 * 1536);
    size_t r  = e % (512 * 1536);
    size_t k  = r / 1536;
    size_t j  = r % 1536;
    const float* src = (j < 512) ? Wq : (j < 1024) ? Wk : Wv;
    size_t jj = j & 511;
    float4 v = *(const float4*)(src + l * 262144 + k * 512 + jj);
    v.x = tf32r(v.x); v.y = tf32r(v.y); v.z = tf32r(v.z); v.w = tf32r(v.w);
    *(float4*)(dst + e) = v;
}

__global__ void pack_qkv_b(const float* __restrict__ bq, const float* __restrict__ bk,
                           const float* __restrict__ bv, float* __restrict__ dst) {
    int i = blockIdx.x * 256 + threadIdx.x;     // over L*1536
    int l = i / 1536;
    int j = i % 1536;
    const float* src = (j < 512) ? bq : (j < 1024) ? bk : bv;
    dst[i] = src[l * 512 + (j & 511)];
}

// ---------------------------------------------------------------------------
// Embedding: h = emb[ids]*sqrt(D) + pe[s]   (writes fp32 + rounded copies)
// ---------------------------------------------------------------------------
__global__ void embed_kernel(const int* __restrict__ ids,
                             const float* __restrict__ emb,
                             const float* __restrict__ pe,
                             float* __restrict__ h, float* __restrict__ hr)
{
    int i = blockIdx.x * blockDim.x + threadIdx.x;
    int row = i >> 7;
    int d4  = (i & 127) << 2;
    int s   = row & (NS - 1);
    int tok = ids[row];
    const float SC = 22.62741699796952f;
    float4 e = *(const float4*)(emb + (size_t)tok * ND + d4);
    float4 p = *(const float4*)(pe  + (size_t)s   * ND + d4);
    float4 r;
    r.x = e.x * SC + p.x; r.y = e.y * SC + p.y;
    r.z = e.z * SC + p.z; r.w = e.w * SC + p.w;
    *(float4*)(h + (size_t)row * ND + d4) = r;
    float4 rr = make_float4(tf32r(r.x), tf32r(r.y), tf32r(r.z), tf32r(r.w));
    *(float4*)(hr + (size_t)row * ND + d4) = rr;
}

// ---------------------------------------------------------------------------
// TF32 MMA GEMM with cp.async 3-stage pipeline.
// C[M,N] = A[M,K] @ W[K,N] + bias (+R) (+ReLU) (+tf32 round of output)
// Inputs A, W must be pre-rounded to tf32 values.
// 128x128 tile, BK=32, 256 threads = 8 warps (4m x 2n), warp tile 32x64.
// ---------------------------------------------------------------------------
#define BKG 32
#define ASTR 36
#define BSTR 132
#define AST (128*ASTR)     // 4608 floats / stage
#define BST (BKG*BSTR)     // 4224 floats / stage
#define STG 3
#define GEMM_SMEM ((AST+BST)*STG*4)

template<bool RELU, bool RES, bool ROUND>
__global__ void __launch_bounds__(256, 2) mma_gemm(
    const float* __restrict__ A, const float* __restrict__ W,
    const float* __restrict__ bias, const float* __restrict__ R,
    float* __restrict__ C, int M, int N, int K)
{
    extern __shared__ float smg[];
    float* As = smg;                 // [STG][128][ASTR]
    float* Bs = smg + STG * AST;     // [STG][BKG][BSTR]
    uint32_t aSh = (uint32_t)__cvta_generic_to_shared(As);
    uint32_t bSh = (uint32_t)__cvta_generic_to_shared(Bs);

    const int tid  = threadIdx.x;
    const int lane = tid & 31;
    const int warp = tid >> 5;
    const int wm = (warp >> 1) * 32;
    const int wn = (warp & 1) * 64;
    const int bm = blockIdx.y * 128;
    const int bn = blockIdx.x * 128;
    const int lg = lane >> 2;
    const int lt = lane & 3;

    const int arow = tid >> 1;
    const int acol = (tid & 1) * 16;
    const int brow = tid >> 3;
    const int bcol = (tid & 7) * 16;

    const float* Ap = A + (size_t)(bm + arow) * K + acol;
    const float* Wp = W + (size_t)brow * N + bn + bcol;

    const int nk = K / BKG;

    auto load_stage = [&](int it) {
        int s = it % STG;
        const float* ap = Ap + it * BKG;
        uint32_t ad = aSh + (uint32_t)(s * AST + arow * ASTR + acol) * 4;
        #pragma unroll
        for (int i = 0; i < 4; i++) cpa16(ad + i * 16, ap + i * 4);
        const float* wp = Wp + (size_t)it * BKG * N;
        uint32_t bd = bSh + (uint32_t)(s * BST + brow * BSTR + bcol) * 4;
        #pragma unroll
        for (int i = 0; i < 4; i++) cpa16(bd + i * 16, wp + i * 4);
        cpa_commit();
    };

    float acc[2][8][4];
    #pragma unroll
    for (int mf = 0; mf < 2; mf++)
        #pragma unroll
        for (int nf = 0; nf < 8; nf++)
            #pragma unroll
            for (int i = 0; i < 4; i++) acc[mf][nf][i] = 0.f;

    load_stage(0);
    load_stage(1);

    for (int it = 0; it < nk; it++) {
        cpa_wait1();
        __syncthreads();
        if (it + 2 < nk) load_stage(it + 2);
        else cpa_commit();   // keep pending-group count invariant

        const float* as = As + (it % STG) * AST;
        const float* bs = Bs + (it % STG) * BST;
        #pragma unroll
        for (int kk = 0; kk < BKG; kk += 8) {
            const int kb = kk + lt;
            float af[2][4];
            #pragma unroll
            for (int mf = 0; mf < 2; mf++) {
                int r0 = wm + mf * 16 + lg;
                af[mf][0] = as[r0 * ASTR + kb];
                af[mf][1] = as[(r0 + 8) * ASTR + kb];
                af[mf][2] = as[r0 * ASTR + kb + 4];
                af[mf][3] = as[(r0 + 8) * ASTR + kb + 4];
            }
            #pragma unroll
            for (int nf = 0; nf < 8; nf++) {
                int nc = wn + nf * 8 + lg;
                float bf[2];
                bf[0] = bs[kb * BSTR + nc];
                bf[1] = bs[(kb + 4) * BSTR + nc];
                mma_tf32(acc[0][nf], af[0], bf);
                mma_tf32(acc[1][nf], af[1], bf);
            }
        }
    }

    // Epilogue
    #pragma unroll
    for (int mf = 0; mf < 2; mf++) {
        int r0 = bm + wm + mf * 16 + lg;
        int r1 = r0 + 8;
        #pragma unroll
        for (int nf = 0; nf < 8; nf++) {
            int col = bn + wn + nf * 8 + lt * 2;
            float2 bb = *(const float2*)(bias + col);
            float c0 = acc[mf][nf][0] + bb.x;
            float c1 = acc[mf][nf][1] + bb.y;
            float c2 = acc[mf][nf][2] + bb.x;
            float c3 = acc[mf][nf][3] + bb.y;
            if (RES) {
                float2 ra = *(const float2*)(R + (size_t)r0 * N + col);
                float2 rb = *(const float2*)(R + (size_t)r1 * N + col);
                c0 += ra.x; c1 += ra.y; c2 += rb.x; c3 += rb.y;
            }
            if (RELU) {
                c0 = fmaxf(c0, 0.f); c1 = fmaxf(c1, 0.f);
                c2 = fmaxf(c2, 0.f); c3 = fmaxf(c3, 0.f);
            }
            if (ROUND) {
                c0 = tf32r(c0); c1 = tf32r(c1); c2 = tf32r(c2); c3 = tf32r(c3);
            }
            *(float2*)(C + (size_t)r0 * N + col) = make_float2(c0, c1);
            *(float2*)(C + (size_t)r1 * N + col) = make_float2(c2, c3);
        }
    }
}

// ---------------------------------------------------------------------------
// TF32 MMA flash attention with hi/lo error compensation.
// Scores = Qhi*Khi + Qhi*Klo + Qlo*Khi (exact to ~2^-21); PV = P*(Vhi+Vlo).
// Reference's inverted mask: keep strictly j > i, masked value -1e9 (applied
// after /sqrt(dk) scaling). Fully-masked tiles (t < qb) are skipped except
// for the last Q block, which needs them for row S-1's uniform softmax.
// CTA: 64 Q rows x one (b,h); 128 threads = 4 warps, warp tile m16 x n64.
// Output written tf32-rounded (feeds Wo gemm).
// ---------------------------------------------------------------------------
#define KSTR 68
#define VSTR 72
#define ATTN_SMEM ((2*64*KSTR + 2*64*VSTR)*4)

__global__ void __launch_bounds__(128, 3) attn_mma(
    const float* __restrict__ qkv, float* __restrict__ O)
{
    extern __shared__ float sma[];
    float* sKhi = sma;                       // aliased as sP after QK
    float* sKlo = sKhi + 64 * KSTR;
    float* sVhi = sKlo + 64 * KSTR;
    float* sVlo = sVhi + 64 * VSTR;
    float* sP   = sKhi;

    const int tid  = threadIdx.x;
    const int lane = tid & 31;
    const int warp = tid >> 5;
    const int lg = lane >> 2;
    const int lt = lane & 3;
    const int wm = warp * 16;
    const int qb = blockIdx.x, h = blockIdx.y, b = blockIdx.z;

    const float* Qb = qkv + ((size_t)(b * NS + qb * 64)) * 1536 + h * 64;
    const float* Kb = qkv + ((size_t)b * NS) * 1536 + 512 + h * 64;
    const float* Vb = Kb + 512;

    const int r0 = wm + lg;
    const int r1 = r0 + 8;

    // Load Q fragments (hi/lo split), loop-invariant
    float qhi[8][4], qlo[8][4];
    #pragma unroll
    for (int ks = 0; ks < 8; ks++) {
        int c0 = ks * 8 + lt, c1 = c0 + 4;
        float v;
        v = Qb[(size_t)r0 * 1536 + c0]; qhi[ks][0] = tf32r(v); qlo[ks][0] = tf32r(v - qhi[ks][0]);
        v = Qb[(size_t)r1 * 1536 + c0]; qhi[ks][1] = tf32r(v); qlo[ks][1] = tf32r(v - qhi[ks][1]);
        v = Qb[(size_t)r0 * 1536 + c1]; qhi[ks][2] = tf32r(v); qlo[ks][2] = tf32r(v - qhi[ks][2]);
        v = Qb[(size_t)r1 * 1536 + c1]; qhi[ks][3] = tf32r(v); qlo[ks][3] = tf32r(v - qhi[ks][3]);
    }

    float m0 = -1e30f, m1 = -1e30f, l0 = 0.f, l1 = 0.f;
    float oA[8][4];
    #pragma unroll
    for (int nf = 0; nf < 8; nf++)
        oA[nf][0] = oA[nf][1] = oA[nf][2] = oA[nf][3] = 0.f;

    const int i0 = qb * 64 + r0;
    const int i1 = i0 + 8;

    const int t0 = (qb == (NS / 64 - 1)) ? 0 : qb;
    for (int t = t0; t < NS / 64; t++) {
        // Cooperative K/V tile load with hi/lo split
        {
            int r  = tid >> 1;
            int cb = (tid & 1) * 32;
            const float* kp = Kb + (size_t)(t * 64 + r) * 1536 + cb;
            const float* vp = Vb + (size_t)(t * 64 + r) * 1536 + cb;
            #pragma unroll
            for (int i = 0; i < 8; i++) {
                float4 kv = *(const float4*)(kp + i * 4);
                float4 hi, lo;
                hi.x = tf32r(kv.x); lo.x = tf32r(kv.x - hi.x);
                hi.y = tf32r(kv.y); lo.y = tf32r(kv.y - hi.y);
                hi.z = tf32r(kv.z); lo.z = tf32r(kv.z - hi.z);
                hi.w = tf32r(kv.w); lo.w = tf32r(kv.w - hi.w);
                *(float4*)&sKhi[r * KSTR + cb + i * 4] = hi;
                *(float4*)&sKlo[r * KSTR + cb + i * 4] = lo;
                float4 vv = *(const float4*)(vp + i * 4);
                hi.x = tf32r(vv.x); lo.x = tf32r(vv.x - hi.x);
                hi.y = tf32r(vv.y); lo.y = tf32r(vv.y - hi.y);
                hi.z = tf32r(vv.z); lo.z = tf32r(vv.z - hi.z);
                hi.w = tf32r(vv.w); lo.w = tf32r(vv.w - hi.w);
                *(float4*)&sVhi[r * VSTR + cb + i * 4] = hi;
                *(float4*)&sVlo[r * VSTR + cb + i * 4] = lo;
            }
        }
        __syncthreads();

        // Scores: Qhi*Khi + Qhi*Klo + Qlo*Khi
        float s[8][4];
        #pragma unroll
        for (int nf = 0; nf < 8; nf++)
            s[nf][0] = s[nf][1] = s[nf][2] = s[nf][3] = 0.f;
        #pragma unroll
        for (int ks = 0; ks < 8; ks++) {
            #pragma unroll
            for (int nf = 0; nf < 8; nf++) {
                int n = nf * 8 + lg;
                float bh[2], bl[2];
                bh[0] = sKhi[n * KSTR + ks * 8 + lt];
                bh[1] = sKhi[n * KSTR + ks * 8 + lt + 4];
                bl[0] = sKlo[n * KSTR + ks * 8 + lt];
                bl[1] = sKlo[n * KSTR + ks * 8 + lt + 4];
                mma_tf32(s[nf], qhi[ks], bh);
                mma_tf32(s[nf], qhi[ks], bl);
                mma_tf32(s[nf], qlo[ks], bh);
            }
        }

        // Mask + online softmax
        const bool diag = (t <= qb);
        #pragma unroll
        for (int nf = 0; nf < 8; nf++) {
            if (diag) {
                int j0 = t * 64 + nf * 8 + lt * 2;
                s[nf][0] = (j0     > i0) ? s[nf][0] * 0.125f : -1e9f;
                s[nf][1] = (j0 + 1 > i0) ? s[nf][1] * 0.125f : -1e9f;
                s[nf][2] = (j0     > i1) ? s[nf][2] * 0.125f : -1e9f;
                s[nf][3] = (j0 + 1 > i1) ? s[nf][3] * 0.125f : -1e9f;
            } else {
                s[nf][0] *= 0.125f; s[nf][1] *= 0.125f;
                s[nf][2] *= 0.125f; s[nf][3] *= 0.125f;
            }
        }
        float mx0 = -1e30f, mx1 = -1e30f;
        #pragma unroll
        for (int nf = 0; nf < 8; nf++) {
            mx0 = fmaxf(mx0, fmaxf(s[nf][0], s[nf][1]));
            mx1 = fmaxf(mx1, fmaxf(s[nf][2], s[nf][3]));
        }
        mx0 = fmaxf(mx0, __shfl_xor_sync(0xffffffffu, mx0, 1));
        mx0 = fmaxf(mx0, __shfl_xor_sync(0xffffffffu, mx0, 2));
        mx1 = fmaxf(mx1, __shfl_xor_sync(0xffffffffu, mx1, 1));
        mx1 = fmaxf(mx1, __shfl_xor_sync(0xffffffffu, mx1, 2));
        float mn0 = fmaxf(m0, mx0), mn1 = fmaxf(m1, mx1);
        float corr0 = __expf(m0 - mn0), corr1 = __expf(m1 - mn1);
        m0 = mn0; m1 = mn1;
        float ls0 = 0.f, ls1 = 0.f;
        #pragma unroll
        for (int nf = 0; nf < 8; nf++) {
            float p;
            p = __expf(s[nf][0] - mn0); s[nf][0] = p; ls0 += p;
            p = __expf(s[nf][1] - mn0); s[nf][1] = p; ls0 += p;
            p = __expf(s[nf][2] - mn1); s[nf][2] = p; ls1 += p;
            p = __expf(s[nf][3] - mn1); s[nf][3] = p; ls1 += p;
        }
        ls0 += __shfl_xor_sync(0xffffffffu, ls0, 1);
        ls0 += __shfl_xor_sync(0xffffffffu, ls0, 2);
        ls1 += __shfl_xor_sync(0xffffffffu, ls1, 1);
        ls1 += __shfl_xor_sync(0xffffffffu, ls1, 2);
        l0 = l0 * corr0 + ls0;
        l1 = l1 * corr1 + ls1;
        #pragma unroll
        for (int nf = 0; nf < 8; nf++) {
            oA[nf][0] *= corr0; oA[nf][1] *= corr0;
            oA[nf][2] *= corr1; oA[nf][3] *= corr1;
        }
        __syncthreads();   // all warps done reading sKhi/sKlo

        // Store P (tf32-rounded) into sP (aliases sKhi)
        #pragma unroll
        for (int nf = 0; nf < 8; nf++) {
            int jl = nf * 8 + lt * 2;
            sP[r0 * KSTR + jl]     = tf32r(s[nf][0]);
            sP[r0 * KSTR + jl + 1] = tf32r(s[nf][1]);
            sP[r1 * KSTR + jl]     = tf32r(s[nf][2]);
            sP[r1 * KSTR + jl + 1] = tf32r(s[nf][3]);
        }
        __syncthreads();

        // O += P @ (Vhi + Vlo)
        #pragma unroll
        for (int ks = 0; ks < 8; ks++) {
            float pa[4];
            pa[0] = sP[r0 * KSTR + ks * 8 + lt];
            pa[1] = sP[r1 * KSTR + ks * 8 + lt];
            pa[2] = sP[r0 * KSTR + ks * 8 + lt + 4];
            pa[3] = sP[r1 * KSTR + ks * 8 + lt + 4];
            #pragma unroll
            for (int nf = 0; nf < 8; nf++) {
                int n = nf * 8 + lg;
                float bh[2], bl[2];
                bh[0] = sVhi[(ks * 8 + lt) * VSTR + n];
                bh[1] = sVhi[(ks * 8 + lt + 4) * VSTR + n];
                bl[0] = sVlo[(ks * 8 + lt) * VSTR + n];
                bl[1] = sVlo[(ks * 8 + lt + 4) * VSTR + n];
                mma_tf32(oA[nf], pa, bh);
                mma_tf32(oA[nf], pa, bl);
            }
        }
        __syncthreads();   // before next tile overwrites K/V/P
    }

    // Normalize + write (tf32-rounded: feeds Wo gemm)
    float inv0 = 1.0f / l0, inv1 = 1.0f / l1;
    float* Op = O + ((size_t)(b * NS + qb * 64)) * ND + h * 64;
    #pragma unroll
    for (int nf = 0; nf < 8; nf++) {
        int d = nf * 8 + lt * 2;
        *(float2*)(Op + (size_t)r0 * ND + d) =
            make_float2(tf32r(oA[nf][0] * inv0), tf32r(oA[nf][1] * inv0));
        *(float2*)(Op + (size_t)r1 * ND + d) =
            make_float2(tf32r(oA[nf][2] * inv1), tf32r(oA[nf][3] * inv1));
    }
}

// ---------------------------------------------------------------------------
// LayerNorm: warp per row; writes fp32 (residual) + tf32-rounded (gemm input)
// ---------------------------------------------------------------------------
__global__ void ln_kernel(const float* __restrict__ X, const float* __restrict__ gam,
                          const float* __restrict__ bet, float* __restrict__ Yf,
                          float* __restrict__ Yr)
{
    int row  = blockIdx.x * 4 + (threadIdx.x >> 5);
    int lane = threadIdx.x & 31;
    const float* x = X + (size_t)row * ND;
    float4 v[4];
    float sum = 0.f;
    #pragma unroll
    for (int i = 0; i < 4; i++) {
        v[i] = *(const float4*)(x + lane * 4 + i * 128);
        sum += v[i].x + v[i].y + v[i].z + v[i].w;
    }
    #pragma unroll
    for (int off = 16; off; off >>= 1) sum += __shfl_xor_sync(0xffffffffu, sum, off);
    float mu = sum * (1.0f / 512.0f);
    float vs = 0.f;
    #pragma unroll
    for (int i = 0; i < 4; i++) {
        float dx;
        dx = v[i].x - mu; vs += dx * dx;
        dx = v[i].y - mu; vs += dx * dx;
        dx = v[i].z - mu; vs += dx * dx;
        dx = v[i].w - mu; vs += dx * dx;
    }
    #pragma unroll
    for (int off = 16; off; off >>= 1) vs += __shfl_xor_sync(0xffffffffu, vs, off);
    float rstd = rsqrtf(vs * (1.0f / 512.0f) + 1e-5f);
    float* yf = Yf + (size_t)row * ND;
    float* yr = Yr + (size_t)row * ND;
    #pragma unroll
    for (int i = 0; i < 4; i++) {
        float4 g4 = *(const float4*)(gam + lane * 4 + i * 128);
        float4 b4 = *(const float4*)(bet + lane * 4 + i * 128);
        float4 r;
        r.x = (v[i].x - mu) * rstd * g4.x + b4.x;
        r.y = (v[i].y - mu) * rstd * g4.y + b4.y;
        r.z = (v[i].z - mu) * rstd * g4.z + b4.z;
        r.w = (v[i].w - mu) * rstd * g4.w + b4.w;
        *(float4*)(yf + lane * 4 + i * 128) = r;
        float4 rr = make_float4(tf32r(r.x), tf32r(r.y), tf32r(r.z), tf32r(r.w));
        *(float4*)(yr + lane * 4 + i * 128) = rr;
    }
}

// ---------------------------------------------------------------------------
// Host orchestration
// ---------------------------------------------------------------------------
extern "C" void kernel_launch(void* const* d_in, const int* in_sizes, int n_in,
                              void* d_out, int out_size)
{
    const int*   ids  = (const int*)  d_in[0];
    const float* emb  = (const float*)d_in[1];
    const float* pe   = (const float*)d_in[2];
    const float* Wq   = (const float*)d_in[3];
    const float* bq   = (const float*)d_in[4];
    const float* Wk   = (const float*)d_in[5];
    const float* bk   = (const float*)d_in[6];
    const float* Wv   = (const float*)d_in[7];
    const float* bv   = (const float*)d_in[8];
    const float* Wo   = (const float*)d_in[9];
    const float* bo   = (const float*)d_in[10];
    const float* g1   = (const float*)d_in[11];
    const float* be1  = (const float*)d_in[12];
    const float* W1   = (const float*)d_in[13];
    const float* b1   = (const float*)d_in[14];
    const float* W2   = (const float*)d_in[15];
    const float* b2   = (const float*)d_in[16];
    const float* g2   = (const float*)d_in[17];
    const float* be2  = (const float*)d_in[18];
    const float* Wout = (const float*)d_in[19];
    const float* bout = (const float*)d_in[20];
    float* out = (float*)d_out;

    float* scratch = nullptr;
    cudaGetSymbolAddress((void**)&scratch, g_scratch);
    float* h      = scratch;
    float* h_r    = h      + SZ_HD;
    float* o      = h_r    + SZ_HD;
    float* tp     = o      + SZ_HD;
    float* qkv    = tp     + SZ_HD;
    float* ff     = qkv    + SZ_QKV;
    float* Wqkv_r = ff     + SZ_FF;
    float* Wo_r   = Wqkv_r + SZ_WQKV;
    float* W1_r   = Wo_r   + SZ_WO;
    float* W2_r   = W1_r   + SZ_W1;
    float* Wout_r = W2_r   + SZ_W2;
    float* bqkv   = Wout_r + SZ_WOUT;

    static bool attr_done = false;
    if (!attr_done) {
        cudaFuncSetAttribute(mma_gemm<false, false, false>,
                             cudaFuncAttributeMaxDynamicSharedMemorySize, GEMM_SMEM);
        cudaFuncSetAttribute(mma_gemm<false, true, false>,
                             cudaFuncAttributeMaxDynamicSharedMemorySize, GEMM_SMEM);
        cudaFuncSetAttribute(mma_gemm<true, false, true>,
                             cudaFuncAttributeMaxDynamicSharedMemorySize, GEMM_SMEM);
        cudaFuncSetAttribute(attn_mma,
                             cudaFuncAttributeMaxDynamicSharedMemorySize, ATTN_SMEM);
        attr_done = true;
    }

    // Pre-round / pack weights into scratch
    pack_qkv_w<<<(int)(SZ_WQKV / 4 / 256), 256>>>(Wq, Wk, Wv, Wqkv_r);
    pack_qkv_b<<<(int)(SZ_BQKV / 256), 256>>>(bq, bk, bv, bqkv);
    round_copy4<<<(int)(SZ_WO   / 4 / 256), 256>>>(Wo,   Wo_r);
    round_copy4<<<(int)(SZ_W1   / 4 / 256), 256>>>(W1,   W1_r);
    round_copy4<<<(int)(SZ_W2   / 4 / 256), 256>>>(W2,   W2_r);
    round_copy4<<<(int)(SZ_WOUT / 4 / 256), 256>>>(Wout, Wout_r);

    embed_kernel<<<(NM * ND / 4) / 256, 256>>>(ids, emb, pe, h, h_r);

    dim3 gQKV(1536 / 128, NM / 128);
    dim3 gP  (ND   / 128, NM / 128);
    dim3 gF1 (NF   / 128, NM / 128);
    dim3 attG(NS / 64, NH, NB);

    for (int L = 0; L < NL; L++) {
        size_t dd = (size_t)L * ND * ND;
        size_t b_ = (size_t)L * ND;
        mma_gemm<false, false, false><<<gQKV, 256, GEMM_SMEM>>>(
            h_r, Wqkv_r + (size_t)L * 512 * 1536, bqkv + (size_t)L * 1536,
            nullptr, qkv, NM, 1536, ND);
        attn_mma<<<attG, 128, ATTN_SMEM>>>(qkv, o);
        mma_gemm<false, true, false><<<gP, 256, GEMM_SMEM>>>(
            o, Wo_r + dd, bo + b_, h, tp, NM, ND, ND);
        ln_kernel<<<NM / 4, 128>>>(tp, g1 + b_, be1 + b_, h, h_r);
        mma_gemm<true, false, true><<<gF1, 256, GEMM_SMEM>>>(
            h_r, W1_r + (size_t)L * ND * NF, b1 + (size_t)L * NF,
            nullptr, ff, NM, NF, ND);
        mma_gemm<false, true, false><<<gP, 256, GEMM_SMEM>>>(
            ff, W2_r + (size_t)L * NF * ND, b2 + b_, h, tp, NM, ND, NF);
        ln_kernel<<<NM / 4, 128>>>(tp, g2 + b_, be2 + b_, h, h_r);
    }
    mma_gemm<false, false, false><<<dim3(NV / 128, NM / 128), 256, GEMM_SMEM>>>(
        h_r, Wout_r, bout, nullptr, out, NM, NV, ND);
}